// round 13
// baseline (speedup 1.0000x reference)
#include <cuda_runtime.h>
#include <cstddef>
#include <cstdint>

// Problem constants (fixed by the reference)
#define NSLOTS   262144      // D
#define DIM      128         // d
#define KHN      32          // K*H
#define BROWS    32768       // B
#define WSCALE   0.17677669529663687f  // 1/sqrt(32)
#define EPS_F    1e-8f

// Scratch (inputs memory/counts are zeros but we must not mutate d_in —
// graph replays would accumulate). 128MB + 1MB static device arrays.
__device__ float g_mem[(size_t)NSLOTS * DIM];
__device__ float g_cnt[NSLOTS];

// ---------------------------------------------------------------------------
// Phase 0: zero the scratch (float4 grid-stride)
// ---------------------------------------------------------------------------
__global__ void bbpm_zero_kernel() {
    const size_t stride = (size_t)gridDim.x * blockDim.x;
    size_t i = (size_t)blockIdx.x * blockDim.x + threadIdx.x;
    float4 z = make_float4(0.f, 0.f, 0.f, 0.f);
    float4* m = reinterpret_cast<float4*>(g_mem);
    const size_t nm = (size_t)NSLOTS * DIM / 4;
    for (size_t k = i; k < nm; k += stride) m[k] = z;
    float4* c = reinterpret_cast<float4*>(g_cnt);
    const size_t nc = NSLOTS / 4;
    for (size_t k = i; k < nc; k += stride) c[k] = z;
}

// ---------------------------------------------------------------------------
// Phase 1: scatter-add. One warp per row b.
//   lane holds values[b, lane*4 .. lane*4+3] * SCALE (float4)
//   lane j holds indices[b, j]; broadcast via shfl; vector red per slot.
// ---------------------------------------------------------------------------
__global__ void bbpm_scatter_kernel(const int* __restrict__ indices,
                                    const float* __restrict__ values) {
    const int gtid = blockIdx.x * blockDim.x + threadIdx.x;
    const int warp = gtid >> 5;
    const int lane = gtid & 31;
    if (warp >= BROWS) return;

    float4 v = reinterpret_cast<const float4*>(values)[(size_t)warp * 32 + lane];
    v.x *= WSCALE; v.y *= WSCALE; v.z *= WSCALE; v.w *= WSCALE;

    const int myidx = indices[(size_t)warp * KHN + lane];
    atomicAdd(&g_cnt[myidx], 1.0f);

#pragma unroll
    for (int j = 0; j < KHN; ++j) {
        const int idx = __shfl_sync(0xffffffffu, myidx, j);
        float* p = &g_mem[(size_t)idx * DIM + lane * 4];
        asm volatile("red.global.add.v4.f32 [%0], {%1, %2, %3, %4};"
                     :: "l"(p), "f"(v.x), "f"(v.y), "f"(v.z), "f"(v.w)
                     : "memory");
    }
}

// ---------------------------------------------------------------------------
// Phase 2: gather + debias + mean. One warp per row b.
// ---------------------------------------------------------------------------
__global__ void bbpm_gather_kernel(const int* __restrict__ indices,
                                   float* __restrict__ out) {
    const int gtid = blockIdx.x * blockDim.x + threadIdx.x;
    const int warp = gtid >> 5;
    const int lane = gtid & 31;
    if (warp >= BROWS) return;

    const int myidx = indices[(size_t)warp * KHN + lane];
    const float cnt = __ldg(&g_cnt[myidx]);
    const float inv = 1.0f / (cnt + EPS_F);

    float4 acc = make_float4(0.f, 0.f, 0.f, 0.f);
    const float4* mem4 = reinterpret_cast<const float4*>(g_mem);

#pragma unroll
    for (int j = 0; j < KHN; ++j) {
        const int   idx = __shfl_sync(0xffffffffu, myidx, j);
        const float w   = __shfl_sync(0xffffffffu, inv,   j);
        float4 g = __ldg(&mem4[(size_t)idx * 32 + lane]);
        acc.x += g.x * w;
        acc.y += g.y * w;
        acc.z += g.z * w;
        acc.w += g.w * w;
    }

    const float m = 1.0f / (float)KHN;
    float4 r = make_float4(acc.x * m, acc.y * m, acc.z * m, acc.w * m);
    reinterpret_cast<float4*>(out)[(size_t)warp * 32 + lane] = r;
}

// ---------------------------------------------------------------------------
// Launch: indices = d_in[0] (int32 [B,KH]), values = d_in[1] (f32 [B,d]),
// memory = d_in[2], counts = d_in[3] (both zero — unused; scratch instead).
// Output: f32 [B,d].
// ---------------------------------------------------------------------------
extern "C" void kernel_launch(void* const* d_in, const int* in_sizes, int n_in,
                              void* d_out, int out_size) {
    (void)in_sizes; (void)n_in; (void)out_size;
    const int*   indices = (const int*)d_in[0];
    const float* values  = (const float*)d_in[1];
    float*       out     = (float*)d_out;

    bbpm_zero_kernel<<<2048, 256>>>();

    // One warp per row: BROWS warps, 8 warps/block
    const int blocks = BROWS / 8;   // 4096
    bbpm_scatter_kernel<<<blocks, 256>>>(indices, values);
    bbpm_gather_kernel<<<blocks, 256>>>(indices, out);
}

// round 15
// speedup vs baseline: 1.0091x; 1.0091x over previous
#include <cuda_runtime.h>
#include <cstddef>
#include <cstdint>

// Problem constants (fixed by the reference)
#define NSLOTS   262144      // D
#define DIM      128         // d
#define KHN      32          // K*H
#define BROWS    32768       // B
#define WSCALE   0.17677669529663687f  // 1/sqrt(32)
#define EPS_F    1e-8f

// Scratch (inputs memory/counts are zeros but we must not mutate d_in —
// graph replays would accumulate). 128MB + 1MB static device arrays.
__device__ float g_mem[(size_t)NSLOTS * DIM];
__device__ float g_cnt[NSLOTS];

// ---------------------------------------------------------------------------
// Phase 0: zero the scratch (float4 grid-stride)
// ---------------------------------------------------------------------------
__global__ void bbpm_zero_kernel() {
    const size_t stride = (size_t)gridDim.x * blockDim.x;
    size_t i = (size_t)blockIdx.x * blockDim.x + threadIdx.x;
    float4 z = make_float4(0.f, 0.f, 0.f, 0.f);
    float4* m = reinterpret_cast<float4*>(g_mem);
    const size_t nm = (size_t)NSLOTS * DIM / 4;
    for (size_t k = i; k < nm; k += stride) m[k] = z;
    float4* c = reinterpret_cast<float4*>(g_cnt);
    const size_t nc = NSLOTS / 4;
    for (size_t k = i; k < nc; k += stride) c[k] = z;
}

// ---------------------------------------------------------------------------
// Phase 1: scatter-add. One warp per row b.
//   lane holds values[b, lane*4 .. lane*4+3] * SCALE (float4)
//   lane j holds indices[b, j]; broadcast via shfl; vector red per slot.
// ---------------------------------------------------------------------------
__global__ void bbpm_scatter_kernel(const int* __restrict__ indices,
                                    const float* __restrict__ values) {
    const int gtid = blockIdx.x * blockDim.x + threadIdx.x;
    const int warp = gtid >> 5;
    const int lane = gtid & 31;
    if (warp >= BROWS) return;

    float4 v = reinterpret_cast<const float4*>(values)[(size_t)warp * 32 + lane];
    v.x *= WSCALE; v.y *= WSCALE; v.z *= WSCALE; v.w *= WSCALE;

    const int myidx = indices[(size_t)warp * KHN + lane];
    atomicAdd(&g_cnt[myidx], 1.0f);

#pragma unroll
    for (int j = 0; j < KHN; ++j) {
        const int idx = __shfl_sync(0xffffffffu, myidx, j);
        float* p = &g_mem[(size_t)idx * DIM + lane * 4];
        asm volatile("red.global.add.v4.f32 [%0], {%1, %2, %3, %4};"
                     :: "l"(p), "f"(v.x), "f"(v.y), "f"(v.z), "f"(v.w)
                     : "memory");
    }
}

// ---------------------------------------------------------------------------
// Phase 2: gather + debias + mean. One warp per row b.
// ---------------------------------------------------------------------------
__global__ void bbpm_gather_kernel(const int* __restrict__ indices,
                                   float* __restrict__ out) {
    const int gtid = blockIdx.x * blockDim.x + threadIdx.x;
    const int warp = gtid >> 5;
    const int lane = gtid & 31;
    if (warp >= BROWS) return;

    const int myidx = indices[(size_t)warp * KHN + lane];
    const float cnt = __ldg(&g_cnt[myidx]);
    const float inv = 1.0f / (cnt + EPS_F);

    float4 acc = make_float4(0.f, 0.f, 0.f, 0.f);
    const float4* mem4 = reinterpret_cast<const float4*>(g_mem);

#pragma unroll
    for (int j = 0; j < KHN; ++j) {
        const int   idx = __shfl_sync(0xffffffffu, myidx, j);
        const float w   = __shfl_sync(0xffffffffu, inv,   j);
        float4 g = __ldg(&mem4[(size_t)idx * 32 + lane]);
        acc.x += g.x * w;
        acc.y += g.y * w;
        acc.z += g.z * w;
        acc.w += g.w * w;
    }

    const float m = 1.0f / (float)KHN;
    float4 r = make_float4(acc.x * m, acc.y * m, acc.z * m, acc.w * m);
    reinterpret_cast<float4*>(out)[(size_t)warp * 32 + lane] = r;
}

// ---------------------------------------------------------------------------
// Launch: indices = d_in[0] (int32 [B,KH]), values = d_in[1] (f32 [B,d]),
// memory = d_in[2], counts = d_in[3] (both zero — unused; scratch instead).
// Output: f32 [B,d].
// ---------------------------------------------------------------------------
extern "C" void kernel_launch(void* const* d_in, const int* in_sizes, int n_in,
                              void* d_out, int out_size) {
    (void)in_sizes; (void)n_in; (void)out_size;
    const int*   indices = (const int*)d_in[0];
    const float* values  = (const float*)d_in[1];
    float*       out     = (float*)d_out;

    bbpm_zero_kernel<<<2048, 256>>>();

    // One warp per row: BROWS warps, 8 warps/block
    const int blocks = BROWS / 8;   // 4096
    bbpm_scatter_kernel<<<blocks, 256>>>(indices, values);
    bbpm_gather_kernel<<<blocks, 256>>>(indices, out);
}